// round 15
// baseline (speedup 1.0000x reference)
#include <cuda_runtime.h>
#include <cuda_bf16.h>
#include <math.h>
#include <stdint.h>

#define D_MODEL 1024
#define SEQ     2048
#define BATCH   2
#define NHEAD   16
#define DH      64
#define D3      (3 * D_MODEL)
#define MTOT    (BATCH * SEQ)

__device__ __nv_bfloat16 g_qkvh[MTOT * D3];
__device__ __nv_bfloat16 g_qkvl[MTOT * D3];
__device__ __nv_bfloat16 g_ah[MTOT * D_MODEL];
__device__ __nv_bfloat16 g_al[MTOT * D_MODEL];
__device__ __nv_bfloat16 g_bh[D3 * D_MODEL];
__device__ __nv_bfloat16 g_bl[D3 * D_MODEL];

#define NEG_INF __int_as_float(0xff800000)

// ---------------- helpers ----------------
__device__ __forceinline__ uint32_t smem_u32(const void* p) {
    uint32_t a;
    asm("{ .reg .u64 t; cvta.to.shared.u64 t, %1; cvt.u32.u64 %0, t; }" : "=r"(a) : "l"(p));
    return a;
}
__device__ __forceinline__ void ldsm_x4(uint32_t* r, uint32_t addr) {
    asm volatile("ldmatrix.sync.aligned.m8n8.x4.shared.b16 {%0,%1,%2,%3}, [%4];"
                 : "=r"(r[0]), "=r"(r[1]), "=r"(r[2]), "=r"(r[3]) : "r"(addr));
}
__device__ __forceinline__ void ldsm_x4_t(uint32_t* r, uint32_t addr) {
    asm volatile("ldmatrix.sync.aligned.m8n8.x4.trans.shared.b16 {%0,%1,%2,%3}, [%4];"
                 : "=r"(r[0]), "=r"(r[1]), "=r"(r[2]), "=r"(r[3]) : "r"(addr));
}
__device__ __forceinline__ void mma16816(float* d, const uint32_t* a, uint32_t b0, uint32_t b1) {
    asm volatile("mma.sync.aligned.m16n8k16.row.col.f32.bf16.bf16.f32 "
                 "{%0,%1,%2,%3}, {%4,%5,%6,%7}, {%8,%9}, {%0,%1,%2,%3};"
                 : "+f"(d[0]), "+f"(d[1]), "+f"(d[2]), "+f"(d[3])
                 : "r"(a[0]), "r"(a[1]), "r"(a[2]), "r"(a[3]), "r"(b0), "r"(b1));
}
__device__ __forceinline__ float ex2(float x) {
    float r;
    asm("ex2.approx.ftz.f32 %0, %1;" : "=f"(r) : "f"(x));
    return r;
}
__device__ __forceinline__ uint32_t bf2pack(float a, float b) {
    __nv_bfloat162 t = __floats2bfloat162_rn(a, b);
    return *reinterpret_cast<uint32_t*>(&t);
}
__device__ __forceinline__ void split1(float v, float& hf, float& lf) {
    __nv_bfloat16 h = __float2bfloat16_rn(v);
    hf = __bfloat162float(h);
    lf = v - hf;
}

// ---------------- conversion kernels ----------------
__global__ void split_kernel(const float* __restrict__ in,
                             __nv_bfloat16* __restrict__ hi,
                             __nv_bfloat16* __restrict__ lo, int n4)
{
    int i = blockIdx.x * blockDim.x + threadIdx.x;
    if (i >= n4) return;
    float4 v = reinterpret_cast<const float4*>(in)[i];
    float f[4] = {v.x, v.y, v.z, v.w};
    float h[4], l[4];
#pragma unroll
    for (int j = 0; j < 4; j++) split1(f[j], h[j], l[j]);
    reinterpret_cast<uint32_t*>(hi)[2*i]   = bf2pack(h[0], h[1]);
    reinterpret_cast<uint32_t*>(hi)[2*i+1] = bf2pack(h[2], h[3]);
    reinterpret_cast<uint32_t*>(lo)[2*i]   = bf2pack(l[0], l[1]);
    reinterpret_cast<uint32_t*>(lo)[2*i+1] = bf2pack(l[2], l[3]);
}

__global__ void transpose_split_kernel(const float* __restrict__ W,
                                       __nv_bfloat16* __restrict__ th,
                                       __nv_bfloat16* __restrict__ tl,
                                       int K, int N)
{
    __shared__ float t[32][33];
    int k0 = blockIdx.y * 32, n0 = blockIdx.x * 32;
    int tx = threadIdx.x, ty = threadIdx.y;
#pragma unroll
    for (int r = 0; r < 4; r++) {
        int row = ty + r * 8;
        t[row][tx] = W[(size_t)(k0 + row) * N + n0 + tx];
    }
    __syncthreads();
#pragma unroll
    for (int r = 0; r < 4; r++) {
        int nn = ty + r * 8;
        float v = t[tx][nn], h, l;
        split1(v, h, l);
        size_t o = (size_t)(n0 + nn) * K + k0 + tx;
        th[o] = __float2bfloat16_rn(h);
        tl[o] = __float2bfloat16_rn(l);
    }
}

// ---------------------------------------------------------------------------
// HMMA bf16x3 GEMM — 128x64 tile, 256 threads, 8 warps (4x2), 2 CTAs/SM,
// 3-stage smem ring, SINGLE barrier per K-step, single register stage.
// Invariant at iter ks: regs hold k-step ks+1; stage ks%3 ready in smem.
// ---------------------------------------------------------------------------
#define ROWP 40
#define A_ELEMS (128 * ROWP)            // 5120
#define B_ELEMS (64 * ROWP)             // 2560
#define STAGE_ELEMS (2 * A_ELEMS + 2 * B_ELEMS)   // 15360
#define STAGE_B (STAGE_ELEMS * 2)       // 30720
#define GEMM_SMEM (3 * STAGE_B)         // 92160

template<int SPLIT_OUT>
__global__ __launch_bounds__(256, 2) void gemm_hmma(
    const __nv_bfloat16* __restrict__ Ah, const __nv_bfloat16* __restrict__ Al,
    const __nv_bfloat16* __restrict__ Bh, const __nv_bfloat16* __restrict__ Bl,
    float* __restrict__ C,
    __nv_bfloat16* __restrict__ Ch, __nv_bfloat16* __restrict__ Cl,
    int M, int N, int K)
{
    extern __shared__ __nv_bfloat16 sm[];
    const uint32_t sb = smem_u32(sm);
    const int tid = threadIdx.x, lane = tid & 31, warp = tid >> 5;
    const int wm = warp & 3, wn = warp >> 2;            // 4x2 warp grid
    const int cRow = blockIdx.y * 128, cCol = blockIdx.x * 64;
    const int KSTEPS = K / 32;

    const int tg = lane >> 3, tr = lane & 7;
    const int a_row = ((tg & 1) << 3) + tr, a_col = (tg >> 1) << 3;
    const int b_row = ((tg >> 1) << 3) + tr, b_col = (tg & 1) << 3;

    float acc[2][4][4];
#pragma unroll
    for (int i = 0; i < 2; i++)
#pragma unroll
        for (int j = 0; j < 4; j++)
#pragma unroll
            for (int c = 0; c < 4; c++) acc[i][j][c] = 0.f;

    // loader: 384 rows x 4 uint4 = 1536 uint4, 6 per thread
    uint4 stg[6];
    auto ldg_stage = [&](int k0) {
#pragma unroll
        for (int i = 0; i < 6; i++) {
            const int idx = i * 256 + tid;
            const int row = idx >> 2, c4 = idx & 3;
            const __nv_bfloat16* src;
            int r;
            if (row < 128)      { src = Ah; r = cRow + row; }
            else if (row < 256) { src = Al; r = cRow + row - 128; }
            else if (row < 320) { src = Bh; r = cCol + row - 256; }
            else                { src = Bl; r = cCol + row - 320; }
            stg[i] = *reinterpret_cast<const uint4*>(src + (size_t)r * K + k0 + c4 * 8);
        }
    };
    auto sts_stage = [&](int s) {
        __nv_bfloat16* stp = sm + s * STAGE_ELEMS;
#pragma unroll
        for (int i = 0; i < 6; i++) {
            const int idx = i * 256 + tid;
            const int row = idx >> 2, c4 = idx & 3;
            *reinterpret_cast<uint4*>(stp + row * ROWP + c4 * 8) = stg[i];
        }
    };
    auto compute = [&](int s) {
        const uint32_t stb = sb + s * STAGE_B;
#pragma unroll
        for (int k16 = 0; k16 < 2; k16++) {
            const int kc = k16 * 16;
            uint32_t ah[2][4], al[2][4], rh[2][4], rl[2][4];
#pragma unroll
            for (int mi = 0; mi < 2; mi++) {
                const int row = wm * 32 + mi * 16 + a_row;
                const uint32_t off = (uint32_t)(row * ROWP + kc + a_col) * 2;
                ldsm_x4(ah[mi], stb + off);
                ldsm_x4(al[mi], stb + 2 * A_ELEMS + off);
            }
#pragma unroll
            for (int p = 0; p < 2; p++) {
                const int row = wn * 32 + p * 16 + b_row;
                const uint32_t off = (uint32_t)(row * ROWP + kc + b_col) * 2;
                ldsm_x4(rh[p], stb + 4 * A_ELEMS + off);
                ldsm_x4(rl[p], stb + 4 * A_ELEMS + 2 * B_ELEMS + off);
            }
#pragma unroll
            for (int mi = 0; mi < 2; mi++)
#pragma unroll
                for (int p = 0; p < 2; p++) {
                    mma16816(acc[mi][2*p],   ah[mi], rh[p][0], rh[p][1]);
                    mma16816(acc[mi][2*p+1], ah[mi], rh[p][2], rh[p][3]);
                }
#pragma unroll
            for (int mi = 0; mi < 2; mi++)
#pragma unroll
                for (int p = 0; p < 2; p++) {
                    mma16816(acc[mi][2*p],   ah[mi], rl[p][0], rl[p][1]);
                    mma16816(acc[mi][2*p+1], ah[mi], rl[p][2], rl[p][3]);
                }
#pragma unroll
            for (int mi = 0; mi < 2; mi++)
#pragma unroll
                for (int p = 0; p < 2; p++) {
                    mma16816(acc[mi][2*p],   al[mi], rh[p][0], rh[p][1]);
                    mma16816(acc[mi][2*p+1], al[mi], rh[p][2], rh[p][3]);
                }
        }
    };

    // prologue: stage0 filled; regs hold k-step 1
    ldg_stage(0);
    sts_stage(0);
    if (KSTEPS > 1) ldg_stage(32);
    __syncthreads();

    int sC = 0;   // compute stage = ks % 3
    for (int ks = 0; ks < KSTEPS; ks++) {
        int sN = sC + 1; if (sN == 3) sN = 0;   // (ks+1) % 3
        if (ks + 1 < KSTEPS) sts_stage(sN);     // regs from iter ks-1, landed
        if (ks + 2 < KSTEPS) ldg_stage((ks + 2) * 32);  // reload regs (WAR ok)
        compute(sC);
        __syncthreads();
        sC = sN;
    }

    const int er = lane >> 2, ec = (lane & 3) * 2;
#pragma unroll
    for (int mi = 0; mi < 2; mi++) {
#pragma unroll
        for (int ni = 0; ni < 4; ni++) {
            const int row = cRow + wm * 32 + mi * 16 + er;
            const int col = cCol + wn * 32 + ni * 8 + ec;
            if (SPLIT_OUT) {
                float h0, l0, h1, l1;
                split1(acc[mi][ni][0], h0, l0);
                split1(acc[mi][ni][1], h1, l1);
                const size_t i0 = ((size_t)row * N + col) >> 1;
                reinterpret_cast<uint32_t*>(Ch)[i0] = bf2pack(h0, h1);
                reinterpret_cast<uint32_t*>(Cl)[i0] = bf2pack(l0, l1);
                split1(acc[mi][ni][2], h0, l0);
                split1(acc[mi][ni][3], h1, l1);
                const size_t i1 = ((size_t)(row + 8) * N + col) >> 1;
                reinterpret_cast<uint32_t*>(Ch)[i1] = bf2pack(h0, h1);
                reinterpret_cast<uint32_t*>(Cl)[i1] = bf2pack(l0, l1);
            } else {
                *reinterpret_cast<float2*>(C + (size_t)row * N + col) =
                    make_float2(acc[mi][ni][0], acc[mi][ni][1]);
                *reinterpret_cast<float2*>(C + (size_t)(row + 8) * N + col) =
                    make_float2(acc[mi][ni][2], acc[mi][ni][3]);
            }
        }
    }
}

// ---------------------------------------------------------------------------
// Flash attention — EXACT R11 (best measured: 195 us). FROZEN.
// ---------------------------------------------------------------------------
#define KVSTRIDE 72
#define SMAX 16.0f

__global__ __launch_bounds__(256) void attn_mma_kernel(
    const __nv_bfloat16* __restrict__ qkvh, const __nv_bfloat16* __restrict__ qkvl,
    __nv_bfloat16* __restrict__ outh, __nv_bfloat16* __restrict__ outl)
{
    __shared__ __nv_bfloat16 Kh[64 * KVSTRIDE], Kl[64 * KVSTRIDE];
    __shared__ __nv_bfloat16 Vh[64 * KVSTRIDE], Vl[64 * KVSTRIDE];

    const int bx = (int)gridDim.x - 1 - (int)blockIdx.x;
    const int h  = blockIdx.y;
    const int b  = blockIdx.z;
    const int tid = threadIdx.x, lane = tid & 31, warp = tid >> 5;
    const int qr0 = bx * 128;
    const size_t base = (size_t)(b * SEQ) * D3 + h * DH;

    const int tg = lane >> 3, tr = lane & 7;
    const int ar  = ((tg & 1) << 3) + tr,  acs = (tg >> 1) << 3;
    const int br  = ((tg >> 1) << 3) + tr, bcs = (tg & 1) << 3;

    const uint32_t sKh = smem_u32(Kh), sKl = smem_u32(Kl);
    const uint32_t sVh = smem_u32(Vh), sVl = smem_u32(Vl);

    {
        const int row = tid >> 1, cs = (tid & 1) * 32;
        const size_t g = base + (size_t)(qr0 + row) * D3 + cs;
        __nv_bfloat16* hp = (row < 64 ? Kh : Vh) + (row & 63) * KVSTRIDE + cs;
        __nv_bfloat16* lp = (row < 64 ? Kl : Vl) + (row & 63) * KVSTRIDE + cs;
#pragma unroll
        for (int i = 0; i < 4; i++) {
            *reinterpret_cast<uint4*>(hp + i * 8) = *reinterpret_cast<const uint4*>(qkvh + g + i * 8);
            *reinterpret_cast<uint4*>(lp + i * 8) = *reinterpret_cast<const uint4*>(qkvl + g + i * 8);
        }
    }
    __syncthreads();

    uint32_t qh[4][4], ql[4][4];
    {
        const uint32_t hb = (warp < 4) ? sKh : sVh;
        const uint32_t lb = (warp < 4) ? sKl : sVl;
        const int strip = (warp & 3) * 16;
#pragma unroll
        for (int kc = 0; kc < 4; kc++) {
            uint32_t off = (uint32_t)((strip + ar) * KVSTRIDE + kc * 16 + acs) * 2;
            ldsm_x4(qh[kc], hb + off);
            ldsm_x4(ql[kc], lb + off);
        }
    }
    __syncthreads();

    float O[8][4];
#pragma unroll
    for (int j = 0; j < 8; j++)
#pragma unroll
        for (int c = 0; c < 4; c++) O[j][c] = 0.f;
    float l0 = 0.f, l1 = 0.f;

    const int ntiles = 2 * bx + 2;
    const int lrow = tid >> 2, lcs = (tid & 3) * 16;
    uint4 ldreg[4][2];

    auto ldg_tiles = [&](int kt) {
        const size_t rk = base + (size_t)(kt * 64 + lrow) * D3 + D_MODEL + lcs;
#pragma unroll
        for (int i = 0; i < 2; i++) {
            ldreg[0][i] = *reinterpret_cast<const uint4*>(qkvh + rk + i * 8);
            ldreg[1][i] = *reinterpret_cast<const uint4*>(qkvh + rk + D_MODEL + i * 8);
            ldreg[2][i] = *reinterpret_cast<const uint4*>(qkvl + rk + i * 8);
            ldreg[3][i] = *reinterpret_cast<const uint4*>(qkvl + rk + D_MODEL + i * 8);
        }
    };
    auto sts_tiles = [&]() {
        __nv_bfloat16* dst[4] = {Kh, Vh, Kl, Vl};
#pragma unroll
        for (int t = 0; t < 4; t++)
#pragma unroll
            for (int i = 0; i < 2; i++)
                *reinterpret_cast<uint4*>(dst[t] + lrow * KVSTRIDE + lcs + i * 8) = ldreg[t][i];
    };

    ldg_tiles(0);

    const float SC = 0.125f * 1.4426950408889634f;
    const int wrow = warp * 16 + (lane >> 2);
    const int row0g = qr0 + wrow, row1g = row0g + 8;

    for (int kt = 0; kt < ntiles; kt++) {
        sts_tiles();
        __syncthreads();
        if (kt + 1 < ntiles) ldg_tiles(kt + 1);

        float sc[8][4];
#pragma unroll
        for (int j = 0; j < 8; j++)
#pragma unroll
            for (int c = 0; c < 4; c++) sc[j][c] = 0.f;

#pragma unroll
        for (int kc = 0; kc < 4; kc++) {
#pragma unroll
            for (int n2 = 0; n2 < 2; n2++) {
                const int na = 2 * n2, nb = 2 * n2 + 1;
                uint32_t kha[4], khb[4], kla[4], klb[4];
                {
                    uint32_t offa = (uint32_t)((na * 16 + br) * KVSTRIDE + kc * 16 + bcs) * 2;
                    uint32_t offb = (uint32_t)((nb * 16 + br) * KVSTRIDE + kc * 16 + bcs) * 2;
                    ldsm_x4(kha, sKh + offa);
                    ldsm_x4(khb, sKh + offb);
                    ldsm_x4(kla, sKl + offa);
                    ldsm_x4(klb, sKl + offb);
                }
                mma16816(sc[2*na],   qh[kc], kha[0], kha[1]);
                mma16816(sc[2*na+1], qh[kc], kha[2], kha[3]);
                mma16816(sc[2*nb],   qh[kc], khb[0], khb[1]);
                mma16816(sc[2*nb+1], qh[kc], khb[2], khb[3]);
                mma16816(sc[2*na],   qh[kc], kla[0], kla[1]);
                mma16816(sc[2*na+1], qh[kc], kla[2], kla[3]);
                mma16816(sc[2*nb],   qh[kc], klb[0], klb[1]);
                mma16816(sc[2*nb+1], qh[kc], klb[2], klb[3]);
                mma16816(sc[2*na],   ql[kc], kha[0], kha[1]);
                mma16816(sc[2*na+1], ql[kc], kha[2], kha[3]);
                mma16816(sc[2*nb],   ql[kc], khb[0], khb[1]);
                mma16816(sc[2*nb+1], ql[kc], khb[2], khb[3]);
            }
        }

        const bool need_mask = (kt >= 2 * bx);
        float s0 = 0.f, s1 = 0.f;
#pragma unroll
        for (int f = 0; f < 8; f++) {
            const int colb = kt * 64 + f * 8 + ((lane & 3) << 1);
#pragma unroll
            for (int c = 0; c < 4; c++) {
                float t = fmaf(sc[f][c], SC, -SMAX);
                if (need_mask) {
                    int col = colb + (c & 1);
                    int row = (c < 2) ? row0g : row1g;
                    if (col > row) t = -1e30f;
                }
                sc[f][c] = ex2(t);
            }
            s0 += sc[f][0] + sc[f][1];
            s1 += sc[f][2] + sc[f][3];
        }
        s0 += __shfl_xor_sync(0xffffffffu, s0, 1);
        s0 += __shfl_xor_sync(0xffffffffu, s0, 2);
        s1 += __shfl_xor_sync(0xffffffffu, s1, 1);
        s1 += __shfl_xor_sync(0xffffffffu, s1, 2);
        l0 += s0;
        l1 += s1;

        uint32_t pfh[4][4], pfl[4][4];
#pragma unroll
        for (int kc = 0; kc < 4; kc++) {
#pragma unroll
            for (int half = 0; half < 2; half++) {
                const int f = 2 * kc + half;
                float h0, lo0, h1, lo1, h2, lo2, h3, lo3;
                split1(sc[f][0], h0, lo0); split1(sc[f][1], h1, lo1);
                split1(sc[f][2], h2, lo2); split1(sc[f][3], h3, lo3);
                pfh[kc][2*half]   = bf2pack(h0, h1);
                pfh[kc][2*half+1] = bf2pack(h2, h3);
                pfl[kc][2*half]   = bf2pack(lo0, lo1);
                pfl[kc][2*half+1] = bf2pack(lo2, lo3);
            }
        }

#pragma unroll
        for (int kc = 0; kc < 4; kc++) {
#pragma unroll
            for (int n2 = 0; n2 < 2; n2++) {
                const int na = 2 * n2, nb = 2 * n2 + 1;
                uint32_t vha[4], vhb[4], vla[4], vlb[4];
                {
                    uint32_t offa = (uint32_t)((kc * 16 + ar) * KVSTRIDE + na * 16 + acs) * 2;
                    uint32_t offb = (uint32_t)((kc * 16 + ar) * KVSTRIDE + nb * 16 + acs) * 2;
                    ldsm_x4_t(vha, sVh + offa);
                    ldsm_x4_t(vhb, sVh + offb);
                    ldsm_x4_t(vla, sVl + offa);
                    ldsm_x4_t(vlb, sVl + offb);
                }
                mma16816(O[2*na],   pfh[kc], vha[0], vha[1]);
                mma16816(O[2*na+1], pfh[kc], vha[2], vha[3]);
                mma16816(O[2*nb],   pfh[kc], vhb[0], vhb[1]);
                mma16816(O[2*nb+1], pfh[kc], vhb[2], vhb[3]);
                mma16816(O[2*na],   pfh[kc], vla[0], vla[1]);
                mma16816(O[2*na+1], pfh[kc], vla[2], vla[3]);
                mma16816(O[2*nb],   pfh[kc], vlb[0], vlb[1]);
                mma16816(O[2*nb+1], pfh[kc], vlb[2], vlb[3]);
                mma16816(O[2*na],   pfl[kc], vha[0], vha[1]);
                mma16816(O[2*na+1], pfl[kc], vha[2], vha[3]);
                mma16816(O[2*nb],   pfl[kc], vhb[0], vhb[1]);
                mma16816(O[2*nb+1], pfl[kc], vhb[2], vhb[3]);
            }
        }
        __syncthreads();
    }

    const float inv0 = 1.f / l0, inv1 = 1.f / l1;
    const int ec = (lane & 3) << 1;
    const size_t o0 = (size_t)(b * SEQ + row0g) * D_MODEL + h * DH;
    const size_t o1 = (size_t)(b * SEQ + row1g) * D_MODEL + h * DH;
#pragma unroll
    for (int j = 0; j < 8; j++) {
        const int cu = (j * 8 + ec) >> 1;
        float a0 = O[j][0] * inv0, a1 = O[j][1] * inv0;
        float a2 = O[j][2] * inv1, a3 = O[j][3] * inv1;
        float h0, lo0, h1, lo1;
        split1(a0, h0, lo0); split1(a1, h1, lo1);
        reinterpret_cast<uint32_t*>(outh + o0)[cu] = bf2pack(h0, h1);
        reinterpret_cast<uint32_t*>(outl + o0)[cu] = bf2pack(lo0, lo1);
        split1(a2, h0, lo0); split1(a3, h1, lo1);
        reinterpret_cast<uint32_t*>(outh + o1)[cu] = bf2pack(h0, h1);
        reinterpret_cast<uint32_t*>(outl + o1)[cu] = bf2pack(lo0, lo1);
    }
}

// ---------------------------------------------------------------------------
extern "C" void kernel_launch(void* const* d_in, const int* in_sizes, int n_in,
                              void* d_out, int out_size)
{
    const float* x     = (const float*)d_in[0];
    const float* W_in  = (const float*)d_in[1];
    const float* W_out = (const float*)d_in[2];
    float* out = (float*)d_out;

    __nv_bfloat16 *qkvh, *qkvl, *ah, *al, *bh, *bl;
    cudaGetSymbolAddress((void**)&qkvh, g_qkvh);
    cudaGetSymbolAddress((void**)&qkvl, g_qkvl);
    cudaGetSymbolAddress((void**)&ah, g_ah);
    cudaGetSymbolAddress((void**)&al, g_al);
    cudaGetSymbolAddress((void**)&bh, g_bh);
    cudaGetSymbolAddress((void**)&bl, g_bl);

    cudaFuncSetAttribute(gemm_hmma<0>, cudaFuncAttributeMaxDynamicSharedMemorySize, GEMM_SMEM);
    cudaFuncSetAttribute(gemm_hmma<1>, cudaFuncAttributeMaxDynamicSharedMemorySize, GEMM_SMEM);

    {   // split x -> bf16 hi/lo
        int n4 = MTOT * D_MODEL / 4;
        split_kernel<<<(n4 + 255) / 256, 256>>>(x, ah, al, n4);
    }
    {   // W_in -> [3072,1024] hi/lo
        dim3 grid(D3 / 32, D_MODEL / 32);
        transpose_split_kernel<<<grid, dim3(32, 8)>>>(W_in, bh, bl, D_MODEL, D3);
    }
    {   // qkv = x @ W_in, pre-split bf16 output (tiles 128x64)
        dim3 grid(D3 / 64, MTOT / 128);
        gemm_hmma<1><<<grid, 256, GEMM_SMEM>>>(ah, al, bh, bl, nullptr, qkvh, qkvl,
                                               MTOT, D3, D_MODEL);
    }
    {   // causal MHA (R11, frozen)
        dim3 grid(SEQ / 128, NHEAD, BATCH);
        attn_mma_kernel<<<grid, 256>>>(qkvh, qkvl, ah, al);
    }
    {   // W_out -> [1024,1024] hi/lo
        dim3 grid(D_MODEL / 32, D_MODEL / 32);
        transpose_split_kernel<<<grid, dim3(32, 8)>>>(W_out, bh, bl, D_MODEL, D_MODEL);
    }
    {   // out = attn @ W_out, fp32 output (tiles 128x64)
        dim3 grid(D_MODEL / 64, MTOT / 128);
        gemm_hmma<0><<<grid, 256, GEMM_SMEM>>>(ah, al, bh, bl, out, nullptr, nullptr,
                                               MTOT, D_MODEL, D_MODEL);
    }
}

// round 16
// speedup vs baseline: 1.3586x; 1.3586x over previous
#include <cuda_runtime.h>
#include <cuda_fp16.h>
#include <math.h>
#include <stdint.h>

#define D_MODEL 1024
#define SEQ     2048
#define BATCH   2
#define NHEAD   16
#define DH      64
#define D3      (3 * D_MODEL)
#define MTOT    (BATCH * SEQ)

__device__ __half g_qkvh[MTOT * D3];
__device__ __half g_qkvl[MTOT * D3];
__device__ __half g_ah[MTOT * D_MODEL];
__device__ __half g_al[MTOT * D_MODEL];
__device__ __half g_bh[D3 * D_MODEL];

#define NEG_INF __int_as_float(0xff800000)

// ---------------- helpers ----------------
__device__ __forceinline__ uint32_t smem_u32(const void* p) {
    uint32_t a;
    asm("{ .reg .u64 t; cvta.to.shared.u64 t, %1; cvt.u32.u64 %0, t; }" : "=r"(a) : "l"(p));
    return a;
}
__device__ __forceinline__ void ldsm_x4(uint32_t* r, uint32_t addr) {
    asm volatile("ldmatrix.sync.aligned.m8n8.x4.shared.b16 {%0,%1,%2,%3}, [%4];"
                 : "=r"(r[0]), "=r"(r[1]), "=r"(r[2]), "=r"(r[3]) : "r"(addr));
}
__device__ __forceinline__ void ldsm_x4_t(uint32_t* r, uint32_t addr) {
    asm volatile("ldmatrix.sync.aligned.m8n8.x4.trans.shared.b16 {%0,%1,%2,%3}, [%4];"
                 : "=r"(r[0]), "=r"(r[1]), "=r"(r[2]), "=r"(r[3]) : "r"(addr));
}
__device__ __forceinline__ void mma16816(float* d, const uint32_t* a, uint32_t b0, uint32_t b1) {
    asm volatile("mma.sync.aligned.m16n8k16.row.col.f32.f16.f16.f32 "
                 "{%0,%1,%2,%3}, {%4,%5,%6,%7}, {%8,%9}, {%0,%1,%2,%3};"
                 : "+f"(d[0]), "+f"(d[1]), "+f"(d[2]), "+f"(d[3])
                 : "r"(a[0]), "r"(a[1]), "r"(a[2]), "r"(a[3]), "r"(b0), "r"(b1));
}
__device__ __forceinline__ float ex2(float x) {
    float r;
    asm("ex2.approx.ftz.f32 %0, %1;" : "=f"(r) : "f"(x));
    return r;
}
__device__ __forceinline__ uint32_t h2pack(float a, float b) {
    __half2 t = __floats2half2_rn(a, b);
    return *reinterpret_cast<uint32_t*>(&t);
}
__device__ __forceinline__ void split1(float v, float& hf, float& lf) {
    __half h = __float2half_rn(v);
    hf = __half2float(h);
    lf = v - hf;
}

// ---------------- conversion kernels ----------------
__global__ void split_kernel(const float* __restrict__ in,
                             __half* __restrict__ hi,
                             __half* __restrict__ lo, int n4)
{
    int i = blockIdx.x * blockDim.x + threadIdx.x;
    if (i >= n4) return;
    float4 v = reinterpret_cast<const float4*>(in)[i];
    float f[4] = {v.x, v.y, v.z, v.w};
    float h[4], l[4];
#pragma unroll
    for (int j = 0; j < 4; j++) split1(f[j], h[j], l[j]);
    reinterpret_cast<uint32_t*>(hi)[2*i]   = h2pack(h[0], h[1]);
    reinterpret_cast<uint32_t*>(hi)[2*i+1] = h2pack(h[2], h[3]);
    reinterpret_cast<uint32_t*>(lo)[2*i]   = h2pack(l[0], l[1]);
    reinterpret_cast<uint32_t*>(lo)[2*i+1] = h2pack(l[2], l[3]);
}

// W [K,N] fp32 -> W^T [N,K] fp16 (hi only)
__global__ void transpose_h_kernel(const float* __restrict__ W,
                                   __half* __restrict__ th,
                                   int K, int N)
{
    __shared__ float t[32][33];
    int k0 = blockIdx.y * 32, n0 = blockIdx.x * 32;
    int tx = threadIdx.x, ty = threadIdx.y;
#pragma unroll
    for (int r = 0; r < 4; r++) {
        int row = ty + r * 8;
        t[row][tx] = W[(size_t)(k0 + row) * N + n0 + tx];
    }
    __syncthreads();
#pragma unroll
    for (int r = 0; r < 4; r++) {
        int nn = ty + r * 8;
        th[(size_t)(n0 + nn) * K + k0 + tx] = __float2half_rn(t[tx][nn]);
    }
}

// ---------------------------------------------------------------------------
// HMMA fp16 2-pass GEMM: C = (Ah+Al) x Bh^T.  128x64 tile, 256 thr, 8 warps
// (4x2), 2 CTAs/SM, 3-stage ring, single barrier per K-step.
// Stage: [Ah 128x40][Al 128x40][Bh 64x40] = 320 rows.
// ---------------------------------------------------------------------------
#define ROWP 40
#define AT_BYTES (128 * ROWP * 2)       // 10240
#define BT_OFF   (2 * AT_BYTES)         // 20480
#define STAGE_ELEMS (320 * ROWP)        // 12800
#define STAGE_B (STAGE_ELEMS * 2)       // 25600
#define GEMM_SMEM (3 * STAGE_B)         // 76800

template<int SPLIT_OUT>
__global__ __launch_bounds__(256, 2) void gemm_hmma(
    const __half* __restrict__ Ah, const __half* __restrict__ Al,
    const __half* __restrict__ Bh,
    float* __restrict__ C,
    __half* __restrict__ Ch, __half* __restrict__ Cl,
    int M, int N, int K)
{
    extern __shared__ __half sm[];
    const uint32_t sb = smem_u32(sm);
    const int tid = threadIdx.x, lane = tid & 31, warp = tid >> 5;
    const int wm = warp & 3, wn = warp >> 2;
    const int cRow = blockIdx.y * 128, cCol = blockIdx.x * 64;
    const int KSTEPS = K / 32;

    const int tg = lane >> 3, tr = lane & 7;
    const int a_row = ((tg & 1) << 3) + tr, a_col = (tg >> 1) << 3;
    const int b_row = ((tg >> 1) << 3) + tr, b_col = (tg & 1) << 3;

    float acc[2][4][4];
#pragma unroll
    for (int i = 0; i < 2; i++)
#pragma unroll
        for (int j = 0; j < 4; j++)
#pragma unroll
            for (int c = 0; c < 4; c++) acc[i][j][c] = 0.f;

    // loader: 320 rows x 4 uint4 = 1280 uint4, 5 per thread
    uint4 stg[5];
    auto ldg_stage = [&](int k0) {
#pragma unroll
        for (int i = 0; i < 5; i++) {
            const int idx = i * 256 + tid;
            const int row = idx >> 2, c4 = idx & 3;
            const __half* src;
            int r;
            if (row < 128)      { src = Ah; r = cRow + row; }
            else if (row < 256) { src = Al; r = cRow + row - 128; }
            else                { src = Bh; r = cCol + row - 256; }
            stg[i] = *reinterpret_cast<const uint4*>(src + (size_t)r * K + k0 + c4 * 8);
        }
    };
    auto sts_stage = [&](int s) {
        __half* stp = sm + s * STAGE_ELEMS;
#pragma unroll
        for (int i = 0; i < 5; i++) {
            const int idx = i * 256 + tid;
            const int row = idx >> 2, c4 = idx & 3;
            *reinterpret_cast<uint4*>(stp + row * ROWP + c4 * 8) = stg[i];
        }
    };
    auto compute = [&](int s) {
        const uint32_t stb = sb + s * STAGE_B;
#pragma unroll
        for (int k16 = 0; k16 < 2; k16++) {
            const int kc = k16 * 16;
            uint32_t ah[2][4], al[2][4], rh[2][4];
#pragma unroll
            for (int mi = 0; mi < 2; mi++) {
                const int row = wm * 32 + mi * 16 + a_row;
                const uint32_t off = (uint32_t)(row * ROWP + kc + a_col) * 2;
                ldsm_x4(ah[mi], stb + off);
                ldsm_x4(al[mi], stb + AT_BYTES + off);
            }
#pragma unroll
            for (int p = 0; p < 2; p++) {
                const int row = wn * 32 + p * 16 + b_row;
                const uint32_t off = (uint32_t)(row * ROWP + kc + b_col) * 2;
                ldsm_x4(rh[p], stb + BT_OFF + off);
            }
            // pass 1: Ah * Bh
#pragma unroll
            for (int mi = 0; mi < 2; mi++)
#pragma unroll
                for (int p = 0; p < 2; p++) {
                    mma16816(acc[mi][2*p],   ah[mi], rh[p][0], rh[p][1]);
                    mma16816(acc[mi][2*p+1], ah[mi], rh[p][2], rh[p][3]);
                }
            // pass 2: Al * Bh
#pragma unroll
            for (int mi = 0; mi < 2; mi++)
#pragma unroll
                for (int p = 0; p < 2; p++) {
                    mma16816(acc[mi][2*p],   al[mi], rh[p][0], rh[p][1]);
                    mma16816(acc[mi][2*p+1], al[mi], rh[p][2], rh[p][3]);
                }
        }
    };

    ldg_stage(0);
    sts_stage(0);
    if (KSTEPS > 1) ldg_stage(32);
    __syncthreads();

    int sC = 0;
    for (int ks = 0; ks < KSTEPS; ks++) {
        int sN = sC + 1; if (sN == 3) sN = 0;
        if (ks + 1 < KSTEPS) sts_stage(sN);
        if (ks + 2 < KSTEPS) ldg_stage((ks + 2) * 32);
        compute(sC);
        __syncthreads();
        sC = sN;
    }

    const int er = lane >> 2, ec = (lane & 3) * 2;
#pragma unroll
    for (int mi = 0; mi < 2; mi++) {
#pragma unroll
        for (int ni = 0; ni < 4; ni++) {
            const int row = cRow + wm * 32 + mi * 16 + er;
            const int col = cCol + wn * 32 + ni * 8 + ec;
            if (SPLIT_OUT) {
                float h0, l0, h1, l1;
                split1(acc[mi][ni][0], h0, l0);
                split1(acc[mi][ni][1], h1, l1);
                const size_t i0 = ((size_t)row * N + col) >> 1;
                reinterpret_cast<uint32_t*>(Ch)[i0] = h2pack(h0, h1);
                reinterpret_cast<uint32_t*>(Cl)[i0] = h2pack(l0, l1);
                split1(acc[mi][ni][2], h0, l0);
                split1(acc[mi][ni][3], h1, l1);
                const size_t i1 = ((size_t)(row + 8) * N + col) >> 1;
                reinterpret_cast<uint32_t*>(Ch)[i1] = h2pack(h0, h1);
                reinterpret_cast<uint32_t*>(Cl)[i1] = h2pack(l0, l1);
            } else {
                *reinterpret_cast<float2*>(C + (size_t)row * N + col) =
                    make_float2(acc[mi][ni][0], acc[mi][ni][1]);
                *reinterpret_cast<float2*>(C + (size_t)(row + 8) * N + col) =
                    make_float2(acc[mi][ni][2], acc[mi][ni][3]);
            }
        }
    }
}

// ---------------------------------------------------------------------------
// Flash attention — R11 structure, fp16 2-pass: Q=(qh+ql)·Kh, O=(ph+pl)·Vh.
// Smem: Kh, Vh tiles only.
// ---------------------------------------------------------------------------
#define KVSTRIDE 72
#define SMAX 16.0f

__global__ __launch_bounds__(256) void attn_mma_kernel(
    const __half* __restrict__ qkvh, const __half* __restrict__ qkvl,
    __half* __restrict__ outh, __half* __restrict__ outl)
{
    __shared__ __half Kh[64 * KVSTRIDE];
    __shared__ __half Vh[64 * KVSTRIDE];

    const int bx = (int)gridDim.x - 1 - (int)blockIdx.x;
    const int h  = blockIdx.y;
    const int b  = blockIdx.z;
    const int tid = threadIdx.x, lane = tid & 31, warp = tid >> 5;
    const int qr0 = bx * 128;
    const size_t base = (size_t)(b * SEQ) * D3 + h * DH;

    const int tg = lane >> 3, tr = lane & 7;
    const int ar  = ((tg & 1) << 3) + tr,  acs = (tg >> 1) << 3;
    const int br  = ((tg >> 1) << 3) + tr, bcs = (tg & 1) << 3;

    const uint32_t sKh = smem_u32(Kh), sVh = smem_u32(Vh);

    uint32_t qh[4][4], ql[4][4];
    // stage Q hi (rows 0-63 -> Kh, 64-127 -> Vh), build qh frags
    {
        const int row = tid >> 1, cs = (tid & 1) * 32;
        const size_t g = base + (size_t)(qr0 + row) * D3 + cs;
        __half* hp = (row < 64 ? Kh : Vh) + (row & 63) * KVSTRIDE + cs;
#pragma unroll
        for (int i = 0; i < 4; i++)
            *reinterpret_cast<uint4*>(hp + i * 8) = *reinterpret_cast<const uint4*>(qkvh + g + i * 8);
    }
    __syncthreads();
    {
        const uint32_t hb = (warp < 4) ? sKh : sVh;
        const int strip = (warp & 3) * 16;
#pragma unroll
        for (int kc = 0; kc < 4; kc++) {
            uint32_t off = (uint32_t)((strip + ar) * KVSTRIDE + kc * 16 + acs) * 2;
            ldsm_x4(qh[kc], hb + off);
        }
    }
    __syncthreads();
    // stage Q lo, build ql frags
    {
        const int row = tid >> 1, cs = (tid & 1) * 32;
        const size_t g = base + (size_t)(qr0 + row) * D3 + cs;
        __half* lp = (row < 64 ? Kh : Vh) + (row & 63) * KVSTRIDE + cs;
#pragma unroll
        for (int i = 0; i < 4; i++)
            *reinterpret_cast<uint4*>(lp + i * 8) = *reinterpret_cast<const uint4*>(qkvl + g + i * 8);
    }
    __syncthreads();
    {
        const uint32_t lb = (warp < 4) ? sKh : sVh;
        const int strip = (warp & 3) * 16;
#pragma unroll
        for (int kc = 0; kc < 4; kc++) {
            uint32_t off = (uint32_t)((strip + ar) * KVSTRIDE + kc * 16 + acs) * 2;
            ldsm_x4(ql[kc], lb + off);
        }
    }
    __syncthreads();

    float O[8][4];
#pragma unroll
    for (int j = 0; j < 8; j++)
#pragma unroll
        for (int c = 0; c < 4; c++) O[j][c] = 0.f;
    float l0 = 0.f, l1 = 0.f;

    const int ntiles = 2 * bx + 2;
    const int lrow = tid >> 2, lcs = (tid & 3) * 16;
    uint4 ldreg[2][2];   // Kh, Vh

    auto ldg_tiles = [&](int kt) {
        const size_t rk = base + (size_t)(kt * 64 + lrow) * D3 + D_MODEL + lcs;
#pragma unroll
        for (int i = 0; i < 2; i++) {
            ldreg[0][i] = *reinterpret_cast<const uint4*>(qkvh + rk + i * 8);
            ldreg[1][i] = *reinterpret_cast<const uint4*>(qkvh + rk + D_MODEL + i * 8);
        }
    };
    auto sts_tiles = [&]() {
        __half* dst[2] = {Kh, Vh};
#pragma unroll
        for (int t = 0; t < 2; t++)
#pragma unroll
            for (int i = 0; i < 2; i++)
                *reinterpret_cast<uint4*>(dst[t] + lrow * KVSTRIDE + lcs + i * 8) = ldreg[t][i];
    };

    ldg_tiles(0);

    const float SC = 0.125f * 1.4426950408889634f;
    const int wrow = warp * 16 + (lane >> 2);
    const int row0g = qr0 + wrow, row1g = row0g + 8;

    for (int kt = 0; kt < ntiles; kt++) {
        sts_tiles();
        __syncthreads();
        if (kt + 1 < ntiles) ldg_tiles(kt + 1);

        // ---- S = (Qh+Ql) Kh^T ----
        float sc[8][4];
#pragma unroll
        for (int j = 0; j < 8; j++)
#pragma unroll
            for (int c = 0; c < 4; c++) sc[j][c] = 0.f;

#pragma unroll
        for (int kc = 0; kc < 4; kc++) {
#pragma unroll
            for (int n2 = 0; n2 < 2; n2++) {
                const int na = 2 * n2, nb = 2 * n2 + 1;
                uint32_t kha[4], khb[4];
                {
                    uint32_t offa = (uint32_t)((na * 16 + br) * KVSTRIDE + kc * 16 + bcs) * 2;
                    uint32_t offb = (uint32_t)((nb * 16 + br) * KVSTRIDE + kc * 16 + bcs) * 2;
                    ldsm_x4(kha, sKh + offa);
                    ldsm_x4(khb, sKh + offb);
                }
                mma16816(sc[2*na],   qh[kc], kha[0], kha[1]);
                mma16816(sc[2*na+1], qh[kc], kha[2], kha[3]);
                mma16816(sc[2*nb],   qh[kc], khb[0], khb[1]);
                mma16816(sc[2*nb+1], qh[kc], khb[2], khb[3]);
                mma16816(sc[2*na],   ql[kc], kha[0], kha[1]);
                mma16816(sc[2*na+1], ql[kc], kha[2], kha[3]);
                mma16816(sc[2*nb],   ql[kc], khb[0], khb[1]);
                mma16816(sc[2*nb+1], ql[kc], khb[2], khb[3]);
            }
        }

        // ---- static-max softmax ----
        const bool need_mask = (kt >= 2 * bx);
        float s0 = 0.f, s1 = 0.f;
#pragma unroll
        for (int f = 0; f < 8; f++) {
            const int colb = kt * 64 + f * 8 + ((lane & 3) << 1);
#pragma unroll
            for (int c = 0; c < 4; c++) {
                float t = fmaf(sc[f][c], SC, -SMAX);
                if (need_mask) {
                    int col = colb + (c & 1);
                    int row = (c < 2) ? row0g : row1g;
                    if (col > row) t = -1e30f;
                }
                sc[f][c] = ex2(t);
            }
            s0 += sc[f][0] + sc[f][1];
            s1 += sc[f][2] + sc[f][3];
        }
        s0 += __shfl_xor_sync(0xffffffffu, s0, 1);
        s0 += __shfl_xor_sync(0xffffffffu, s0, 2);
        s1 += __shfl_xor_sync(0xffffffffu, s1, 1);
        s1 += __shfl_xor_sync(0xffffffffu, s1, 2);
        l0 += s0;
        l1 += s1;

        // ---- P -> hi/lo A-fragments ----
        uint32_t pfh[4][4], pfl[4][4];
#pragma unroll
        for (int kc = 0; kc < 4; kc++) {
#pragma unroll
            for (int half = 0; half < 2; half++) {
                const int f = 2 * kc + half;
                float h0, lo0, h1, lo1, h2, lo2, h3, lo3;
                split1(sc[f][0], h0, lo0); split1(sc[f][1], h1, lo1);
                split1(sc[f][2], h2, lo2); split1(sc[f][3], h3, lo3);
                pfh[kc][2*half]   = h2pack(h0, h1);
                pfh[kc][2*half+1] = h2pack(h2, h3);
                pfl[kc][2*half]   = h2pack(lo0, lo1);
                pfl[kc][2*half+1] = h2pack(lo2, lo3);
            }
        }

        // ---- O += (Ph+Pl) Vh ----
#pragma unroll
        for (int kc = 0; kc < 4; kc++) {
#pragma unroll
            for (int n2 = 0; n2 < 2; n2++) {
                const int na = 2 * n2, nb = 2 * n2 + 1;
                uint32_t vha[4], vhb[4];
                {
                    uint32_t offa = (uint32_t)((kc * 16 + ar) * KVSTRIDE + na * 16 + acs) * 2;
                    uint32_t offb = (uint32_t)((kc * 16 + ar) * KVSTRIDE + nb * 16 + acs) * 2;
                    ldsm_x4_t(vha, sVh + offa);
                    ldsm_x4_t(vhb, sVh + offb);
                }
                mma16816(O[2*na],   pfh[kc], vha[0], vha[1]);
                mma16816(O[2*na+1], pfh[kc], vha[2], vha[3]);
                mma16816(O[2*nb],   pfh[kc], vhb[0], vhb[1]);
                mma16816(O[2*nb+1], pfh[kc], vhb[2], vhb[3]);
                mma16816(O[2*na],   pfl[kc], vha[0], vha[1]);
                mma16816(O[2*na+1], pfl[kc], vha[2], vha[3]);
                mma16816(O[2*nb],   pfl[kc], vhb[0], vhb[1]);
                mma16816(O[2*nb+1], pfl[kc], vhb[2], vhb[3]);
            }
        }
        __syncthreads();
    }

    // ---- epilogue: write hi/lo fp16 (input to GEMM2) ----
    const float inv0 = 1.f / l0, inv1 = 1.f / l1;
    const int ec = (lane & 3) << 1;
    const size_t o0 = (size_t)(b * SEQ + row0g) * D_MODEL + h * DH;
    const size_t o1 = (size_t)(b * SEQ + row1g) * D_MODEL + h * DH;
#pragma unroll
    for (int j = 0; j < 8; j++) {
        const int cu = (j * 8 + ec) >> 1;
        float a0 = O[j][0] * inv0, a1 = O[j][1] * inv0;
        float a2 = O[j][2] * inv1, a3 = O[j][3] * inv1;
        float h0, lo0, h1, lo1;
        split1(a0, h0, lo0); split1(a1, h1, lo1);
        reinterpret_cast<uint32_t*>(outh + o0)[cu] = h2pack(h0, h1);
        reinterpret_cast<uint32_t*>(outl + o0)[cu] = h2pack(lo0, lo1);
        split1(a2, h0, lo0); split1(a3, h1, lo1);
        reinterpret_cast<uint32_t*>(outh + o1)[cu] = h2pack(h0, h1);
        reinterpret_cast<uint32_t*>(outl + o1)[cu] = h2pack(lo0, lo1);
    }
}

// ---------------------------------------------------------------------------
extern "C" void kernel_launch(void* const* d_in, const int* in_sizes, int n_in,
                              void* d_out, int out_size)
{
    const float* x     = (const float*)d_in[0];
    const float* W_in  = (const float*)d_in[1];
    const float* W_out = (const float*)d_in[2];
    float* out = (float*)d_out;

    __half *qkvh, *qkvl, *ah, *al, *bh;
    cudaGetSymbolAddress((void**)&qkvh, g_qkvh);
    cudaGetSymbolAddress((void**)&qkvl, g_qkvl);
    cudaGetSymbolAddress((void**)&ah, g_ah);
    cudaGetSymbolAddress((void**)&al, g_al);
    cudaGetSymbolAddress((void**)&bh, g_bh);

    cudaFuncSetAttribute(gemm_hmma<0>, cudaFuncAttributeMaxDynamicSharedMemorySize, GEMM_SMEM);
    cudaFuncSetAttribute(gemm_hmma<1>, cudaFuncAttributeMaxDynamicSharedMemorySize, GEMM_SMEM);

    {   // split x -> fp16 hi/lo
        int n4 = MTOT * D_MODEL / 4;
        split_kernel<<<(n4 + 255) / 256, 256>>>(x, ah, al, n4);
    }
    {   // W_in -> [3072,1024] fp16 (hi only)
        dim3 grid(D3 / 32, D_MODEL / 32);
        transpose_h_kernel<<<grid, dim3(32, 8)>>>(W_in, bh, D_MODEL, D3);
    }
    {   // qkv = x @ W_in, pre-split fp16 output (tiles 128x64)
        dim3 grid(D3 / 64, MTOT / 128);
        gemm_hmma<1><<<grid, 256, GEMM_SMEM>>>(ah, al, bh, nullptr, qkvh, qkvl,
                                               MTOT, D3, D_MODEL);
    }
    {   // causal MHA (fp16 2-pass)
        dim3 grid(SEQ / 128, NHEAD, BATCH);
        attn_mma_kernel<<<grid, 256>>>(qkvh, qkvl, ah, al);
    }
    {   // W_out -> [1024,1024] fp16 (hi only)
        dim3 grid(D_MODEL / 32, D_MODEL / 32);
        transpose_h_kernel<<<grid, dim3(32, 8)>>>(W_out, bh, D_MODEL, D_MODEL);
    }
    {   // out = attn @ W_out, fp32 output (tiles 128x64)
        dim3 grid(D_MODEL / 64, MTOT / 128);
        gemm_hmma<0><<<grid, 256, GEMM_SMEM>>>(ah, al, bh, out, nullptr, nullptr,
                                               MTOT, D_MODEL, D_MODEL);
    }
}